// round 16
// baseline (speedup 1.0000x reference)
#include <cuda_runtime.h>
#include <cuda_bf16.h>

#define NB_ITEMS 12000
#define DD 64
#define BB 1024
#define LL 20
#define BKK 10
#define NOLDK 20

#define SIM_OFF   ((size_t)BB * NB_ITEMS)
#define OMIGA_OFF (SIM_OFF + (size_t)NB_ITEMS * NB_ITEMS)

#define SIM_SPLIT 20      /* tiles with by < SIM_SPLIT -> tensor pipe */

// ---------------- scratch (static device globals; no allocation) ----------------
__device__ float g_final_each[4 * BB * DD];
__device__ float g_final[BB * DD];
__device__ float g_Amat[BB * 128];
__device__ float g_Bbig[(size_t)NB_ITEMS * 128];

// ---------------- helpers ----------------
typedef unsigned long long u64;
__device__ __forceinline__ u64 bcast2(float x) {
    u64 r; asm("mov.b64 %0, {%1, %1};" : "=l"(r) : "f"(x)); return r;
}
__device__ __forceinline__ void fma2(u64& d, u64 a, u64 b) {
    asm("fma.rn.f32x2 %0, %1, %2, %0;" : "+l"(d) : "l"(a), "l"(b));
}
__device__ __forceinline__ void unpk2(u64 v, float& lo, float& hi) {
    asm("mov.b64 {%0, %1}, %2;" : "=f"(lo), "=f"(hi) : "l"(v));
}
__device__ __forceinline__ float sigmoidf_(float x) { return 1.f / (1.f + expf(-x)); }

__device__ __forceinline__ void mma_bf16(float* c, const unsigned* a, const unsigned* b) {
    asm("mma.sync.aligned.m16n8k16.row.col.f32.bf16.bf16.f32 "
        "{%0,%1,%2,%3}, {%4,%5,%6,%7}, {%8,%9}, {%0,%1,%2,%3};"
        : "+f"(c[0]), "+f"(c[1]), "+f"(c[2]), "+f"(c[3])
        : "r"(a[0]), "r"(a[1]), "r"(a[2]), "r"(a[3]), "r"(b[0]), "r"(b[1]));
}

// ---------------- prep ----------------
__global__ __launch_bounds__(256) void prep_kernel(
    const float* __restrict__ item_emb, const float* __restrict__ u_w,
    const float* __restrict__ omiga, float* __restrict__ out)
{
    int idx = blockIdx.x * blockDim.x + threadIdx.x;
    if (idx < NB_ITEMS * 128) {
        int e = idx >> 7, k = idx & 127;
        g_Bbig[idx] = (k < 64) ? item_emb[(size_t)(e + 1) * 64 + k]
                               : u_w[(size_t)(k - 64) * NB_ITEMS + e];
    }
    if (idx < NB_ITEMS) out[OMIGA_OFF + idx] = omiga[idx + 1];
}

// ---------------- per-batch front-end (unchanged, proven) ----------------
__global__ __launch_bounds__(256) void batch_kernel(
    const int* __restrict__ click, const int* __restrict__ favor,
    const int* __restrict__ cart, const int* __restrict__ buy,
    const int* __restrict__ userData,
    const float* __restrict__ item_emb, const float* __restrict__ user_emb,
    const float* __restrict__ user_wd, const float* __restrict__ w_mix,
    const float* __restrict__ alpha, const float* __restrict__ gate_w,
    const float* __restrict__ gate_b, const float* __restrict__ Wk,
    const float* __restrict__ bk)
{
    __shared__ float s_bask[4][LL][DD];
    __shared__ int   s_idx[4][LL][BKK];
    __shared__ float s_eu[DD];
    __shared__ float s_scp[4][2][LL];
    __shared__ float s_attn[4][LL];
    __shared__ float s_mask[4][LL];
    __shared__ float s_lvec[4][DD];
    __shared__ float s_s1[4][DD], s_s2[4][DD], s_s3[4][DD], s_fn[4][DD];
    __shared__ float s_g[8];
    __shared__ float s_fm[DD], s_lm[DD];

    int b = blockIdx.x, t = threadIdx.x;
    int lane = t & 31, warp = t >> 5;
    int u = userData[b];
    const int* srcs[4] = {click, favor, cart, buy};

    for (int i = t; i < 4 * LL * BKK; i += 256) {
        int n = i / (LL * BKK), r = i % (LL * BKK);
        s_idx[n][r / BKK][r % BKK] = srcs[n][(size_t)b * LL * BKK + r];
    }
    if (t < 64) s_eu[t] = user_emb[(size_t)u * 64 + t];
    __syncthreads();

    for (int i = t; i < 4 * LL * DD; i += 256) {
        int n = i / (LL * DD), rem = i % (LL * DD), l = rem / DD, d = rem & 63;
        float s = 0.f;
        #pragma unroll
        for (int q = 0; q < BKK; q++) s += item_emb[(size_t)s_idx[n][l][q] * 64 + d];
        s_bask[n][l][d] = s;
    }
    __syncthreads();

    if (t < 80) {
        int n = t / LL, l = t % LL;
        float m = 0.f;
        for (int d = 0; d < DD; d++) m += s_bask[n][l][d];
        s_mask[n][l] = (m != 0.f) ? 1.f : 0.f;
    }

    {
        int n = t >> 6, e = t & 63;
        float acc[LL];
        #pragma unroll
        for (int l = 0; l < LL; l++) acc[l] = bk[n * 64 + e];
        for (int d0 = 0; d0 < DD; d0++) {
            float w = Wk[((size_t)n * 64 + d0) * 64 + e];
            #pragma unroll
            for (int l = 0; l < LL; l++) acc[l] += s_bask[n][l][d0] * w;
        }
        float eu = s_eu[e];
        #pragma unroll
        for (int l = 0; l < LL; l++) {
            float v = fmaxf(acc[l], 0.f) * eu;
            #pragma unroll
            for (int o = 16; o > 0; o >>= 1) v += __shfl_xor_sync(0xffffffffu, v, o);
            if (lane == 0) s_scp[n][e >> 5][l] = v;
        }
    }
    __syncthreads();

    if (warp < 4) {
        int n = warp;
        float sc = -1e30f;
        if (lane < LL) {
            sc = (s_scp[n][0][lane] + s_scp[n][1][lane]) * 0.125f;
            if (s_mask[n][lane] == 0.f) sc = -1e9f;
        }
        float mx = sc;
        #pragma unroll
        for (int o = 16; o > 0; o >>= 1) mx = fmaxf(mx, __shfl_xor_sync(0xffffffffu, mx, o));
        float ex = (lane < LL) ? expf(sc - mx) : 0.f;
        float sm = ex;
        #pragma unroll
        for (int o = 16; o > 0; o >>= 1) sm += __shfl_xor_sync(0xffffffffu, sm, o);
        if (lane < LL) s_attn[n][lane] = ex / sm;
    }
    __syncthreads();

    {
        int n = t >> 6, d = t & 63;
        float lv = 0.f;
        #pragma unroll
        for (int l = 0; l < LL; l++) lv += s_attn[n][l] * s_bask[n][l][d];
        s_lvec[n][d] = lv;
        float w1 = sigmoidf_(user_wd[(size_t)u * 8 + 2 * n]);
        float w2 = sigmoidf_(user_wd[(size_t)u * 8 + 2 * n + 1]);
        float coef = 1.f - w2 * w1;
        float h = s_bask[n][0][d];
        #pragma unroll
        for (int l = 1; l < LL; l++) h = w1 * h + coef * s_bask[n][l][d];
        float s1 = h;
        h = s_bask[n][10][d];
        #pragma unroll
        for (int l = 11; l < LL; l++) h = w1 * h + coef * s_bask[n][l][d];
        float s2 = h;
        float s3 = w1 * s_bask[n][18][d] + coef * s_bask[n][19][d];
        float a0 = alpha[0], a1 = alpha[1];
        float fn = s1 + a0 * (s1 - s2) + a1 * (s1 - s3);
        s_s1[n][d] = s1; s_s2[n][d] = s2; s_s3[n][d] = s3; s_fn[n][d] = fn;
    }
    __syncthreads();

    if (warp < 4) {
        int n = warp;
        float x = s_fn[n][lane] * gate_w[lane] + s_fn[n][lane + 32] * gate_w[lane + 32]
                + s_lvec[n][lane] * gate_w[64 + lane] + s_lvec[n][lane + 32] * gate_w[96 + lane];
        #pragma unroll
        for (int o = 16; o > 0; o >>= 1) x += __shfl_xor_sync(0xffffffffu, x, o);
        if (lane == 0) s_g[n] = sigmoidf_(x + gate_b[0]);
    }
    __syncthreads();

    {
        int n = t >> 6, d = t & 63;
        float g = s_g[n];
        g_final_each[((size_t)n * BB + b) * 64 + d] = g * s_fn[n][d] + (1.f - g) * s_lvec[n][d];
    }

    if (t < 64) {
        int d = t;
        float wmx[4][4];
        #pragma unroll
        for (int i = 0; i < 4; i++) {
            float mx = -1e30f;
            #pragma unroll
            for (int j = 0; j < 4; j++) mx = fmaxf(mx, w_mix[i * 4 + j]);
            float s = 0.f;
            #pragma unroll
            for (int j = 0; j < 4; j++) { wmx[i][j] = expf(w_mix[i * 4 + j] - mx); s += wmx[i][j]; }
            #pragma unroll
            for (int j = 0; j < 4; j++) wmx[i][j] /= s;
        }
        float s1m = 0, s2m = 0, s3m = 0, lm = 0;
        #pragma unroll
        for (int n = 0; n < 4; n++) {
            s1m += wmx[0][n] * s_s1[n][d];
            s2m += wmx[1][n] * s_s2[n][d];
            s3m += wmx[2][n] * s_s3[n][d];
            lm  += wmx[3][n] * s_lvec[n][d];
        }
        float a0 = alpha[0], a1 = alpha[1];
        s_fm[d] = s1m + a0 * (s1m - s2m) + a1 * (s1m - s3m);
        s_lm[d] = lm;
    }
    __syncthreads();

    if (warp == 0) {
        float x = s_fm[lane] * gate_w[lane] + s_fm[lane + 32] * gate_w[lane + 32]
                + s_lm[lane] * gate_w[64 + lane] + s_lm[lane + 32] * gate_w[96 + lane];
        #pragma unroll
        for (int o = 16; o > 0; o >>= 1) x += __shfl_xor_sync(0xffffffffu, x, o);
        if (lane == 0) s_g[4] = sigmoidf_(x + gate_b[0]);
    }
    __syncthreads();

    if (t < 64) {
        float gm = s_g[4];
        float fin = gm * s_fm[t] + (1.f - gm) * s_lm[t];
        g_final[(size_t)b * 64 + t] = fin;
        g_Amat[(size_t)b * 128 + t] = fin;
        g_Amat[(size_t)b * 128 + 64 + t] = s_eu[t];
    }
}

// ---------------- score GEMM on the TENSOR pipe (R15-proven) ----------------
#define SC_PITCH 68
#define SC_SMEM  (4 * 128 * SC_PITCH * 4)

__global__ __launch_bounds__(256) void score_bf16_kernel(
    const float* __restrict__ A, const float* __restrict__ B,
    const float* __restrict__ bias, float* __restrict__ C)
{
    extern __shared__ unsigned su[];
    unsigned* Ahi = su;
    unsigned* Alo = su + 128 * SC_PITCH;
    unsigned* Bhi = su + 2 * 128 * SC_PITCH;
    unsigned* Blo = su + 3 * 128 * SC_PITCH;

    int bx = blockIdx.x, by = blockIdx.y;
    int row0 = by * 128, col0 = bx * 128;
    int t = threadIdx.x, lane = t & 31, warp = t >> 5;

    {
        int lr = t >> 1, half = t & 1;
        int ar = row0 + lr;
        int br = min(col0 + lr, NB_ITEMS - 1);
        const float4* ap = (const float4*)(A + (size_t)ar * 128 + half * 64);
        const float4* bp = (const float4*)(B + (size_t)br * 128 + half * 64);
        #pragma unroll
        for (int i = 0; i < 16; i++) {
            float4 av = ap[i];
            __nv_bfloat162 h0 = __float22bfloat162_rn(make_float2(av.x, av.y));
            float2 hf0 = __bfloat1622float2(h0);
            __nv_bfloat162 l0 = __float22bfloat162_rn(make_float2(av.x - hf0.x, av.y - hf0.y));
            __nv_bfloat162 h1 = __float22bfloat162_rn(make_float2(av.z, av.w));
            float2 hf1 = __bfloat1622float2(h1);
            __nv_bfloat162 l1 = __float22bfloat162_rn(make_float2(av.z - hf1.x, av.w - hf1.y));
            int w = lr * SC_PITCH + half * 32 + i * 2;
            Ahi[w] = *(unsigned*)&h0; Ahi[w + 1] = *(unsigned*)&h1;
            Alo[w] = *(unsigned*)&l0; Alo[w + 1] = *(unsigned*)&l1;

            float4 bv = bp[i];
            __nv_bfloat162 g0 = __float22bfloat162_rn(make_float2(bv.x, bv.y));
            float2 gf0 = __bfloat1622float2(g0);
            __nv_bfloat162 m0 = __float22bfloat162_rn(make_float2(bv.x - gf0.x, bv.y - gf0.y));
            __nv_bfloat162 g1 = __float22bfloat162_rn(make_float2(bv.z, bv.w));
            float2 gf1 = __bfloat1622float2(g1);
            __nv_bfloat162 m1 = __float22bfloat162_rn(make_float2(bv.z - gf1.x, bv.w - gf1.y));
            Bhi[w] = *(unsigned*)&g0; Bhi[w + 1] = *(unsigned*)&g1;
            Blo[w] = *(unsigned*)&m0; Blo[w + 1] = *(unsigned*)&m1;
        }
    }
    __syncthreads();

    float acc[4][4][4];
    #pragma unroll
    for (int mt = 0; mt < 4; mt++)
        #pragma unroll
        for (int nt = 0; nt < 4; nt++)
            #pragma unroll
            for (int q = 0; q < 4; q++) acc[mt][nt][q] = 0.f;

    int wm = warp >> 2, wn = warp & 3;
    int gr = lane >> 2, kq = lane & 3;

    #pragma unroll
    for (int kc = 0; kc < 8; kc++) {
        unsigned ah[4][4], al[4][4], bh[4][2], bl[4][2];
        #pragma unroll
        for (int mt = 0; mt < 4; mt++) {
            int r = wm * 64 + mt * 16 + gr;
            int w0 = r * SC_PITCH + kc * 8 + kq;
            ah[mt][0] = Ahi[w0];                 ah[mt][1] = Ahi[w0 + 8 * SC_PITCH];
            ah[mt][2] = Ahi[w0 + 4];             ah[mt][3] = Ahi[w0 + 8 * SC_PITCH + 4];
            al[mt][0] = Alo[w0];                 al[mt][1] = Alo[w0 + 8 * SC_PITCH];
            al[mt][2] = Alo[w0 + 4];             al[mt][3] = Alo[w0 + 8 * SC_PITCH + 4];
        }
        #pragma unroll
        for (int nt = 0; nt < 4; nt++) {
            int n = wn * 32 + nt * 8 + gr;
            int w0 = n * SC_PITCH + kc * 8 + kq;
            bh[nt][0] = Bhi[w0]; bh[nt][1] = Bhi[w0 + 4];
            bl[nt][0] = Blo[w0]; bl[nt][1] = Blo[w0 + 4];
        }
        #pragma unroll
        for (int mt = 0; mt < 4; mt++)
            #pragma unroll
            for (int nt = 0; nt < 4; nt++) {
                mma_bf16(acc[mt][nt], ah[mt], bh[nt]);
                mma_bf16(acc[mt][nt], ah[mt], bl[nt]);
                mma_bf16(acc[mt][nt], al[mt], bh[nt]);
            }
    }

    #pragma unroll
    for (int mt = 0; mt < 4; mt++)
        #pragma unroll
        for (int nt = 0; nt < 4; nt++) {
            int r = wm * 64 + mt * 16 + gr;
            int c = wn * 32 + nt * 8 + kq * 2;
            int gc = col0 + c;
            size_t b0 = (size_t)(row0 + r) * NB_ITEMS;
            size_t b1 = (size_t)(row0 + r + 8) * NB_ITEMS;
            if (gc < NB_ITEMS)     { float bb = bias[gc];
                                     C[b0 + gc] = acc[mt][nt][0] + bb;
                                     C[b1 + gc] = acc[mt][nt][2] + bb; }
            if (gc + 1 < NB_ITEMS) { float bb = bias[gc + 1];
                                     C[b0 + gc + 1] = acc[mt][nt][1] + bb;
                                     C[b1 + gc + 1] = acc[mt][nt][3] + bb; }
        }
}

// ---------------- sim (fp32 FFMA2, tiles by >= SIM_SPLIT): R9-proven ----------------
#define SIM_SMEM_B (64 * 1024)

__global__ __launch_bounds__(256) void sim_kernel(
    const float* __restrict__ E, float* __restrict__ C)
{
    extern __shared__ float sm[];
    float* As = sm;
    float* Bs = sm + 64 * 128;

    int bx = blockIdx.x, by = blockIdx.y + SIM_SPLIT;
    if (bx < by) return;
    int t = threadIdx.x;
    int tx = t & 15, ty = t >> 4;
    int row0 = by * 128, col0 = bx * 128;
    int Mrows = NB_ITEMS, Ncols = NB_ITEMS;

    {
        int lr = t >> 1, kh = (t & 1) * 32;
        int ar = min(row0 + lr, NB_ITEMS - 1);
        int br = min(col0 + lr, NB_ITEMS - 1);
        const float4* ap = (const float4*)(E + (size_t)ar * 64 + kh);
        const float4* bp = (const float4*)(E + (size_t)br * 64 + kh);
        #pragma unroll
        for (int i = 0; i < 8; i++) {
            float4 a = ap[i];
            float4 b = bp[i];
            int k = kh + i * 4;
            As[(k + 0) * 128 + lr] = a.x; As[(k + 1) * 128 + lr] = a.y;
            As[(k + 2) * 128 + lr] = a.z; As[(k + 3) * 128 + lr] = a.w;
            Bs[(k + 0) * 128 + lr] = b.x; Bs[(k + 1) * 128 + lr] = b.y;
            Bs[(k + 2) * 128 + lr] = b.z; Bs[(k + 3) * 128 + lr] = b.w;
        }
    }
    __syncthreads();

    u64 acc[8][4];
    #pragma unroll
    for (int r = 0; r < 8; r++)
        #pragma unroll
        for (int c = 0; c < 4; c++) acc[r][c] = 0ULL;

    #pragma unroll 8
    for (int k = 0; k < 64; k++) {
        float4 fa0 = *(const float4*)&As[k * 128 + ty * 4];
        float4 fa1 = *(const float4*)&As[k * 128 + 64 + ty * 4];
        const u64* pb0 = (const u64*)&Bs[k * 128 + tx * 4];
        const u64* pb1 = (const u64*)&Bs[k * 128 + 64 + tx * 4];
        u64 bq0 = pb0[0], bq1 = pb0[1], bq2 = pb1[0], bq3 = pb1[1];
        float a[8] = {fa0.x, fa0.y, fa0.z, fa0.w, fa1.x, fa1.y, fa1.z, fa1.w};
        #pragma unroll
        for (int r = 0; r < 8; r++) {
            u64 ar = bcast2(a[r]);
            fma2(acc[r][0], ar, bq0);
            fma2(acc[r][1], ar, bq1);
            fma2(acc[r][2], ar, bq2);
            fma2(acc[r][3], ar, bq3);
        }
    }

    float vv[8][8];
    #pragma unroll
    for (int r = 0; r < 8; r++)
        #pragma unroll
        for (int c = 0; c < 4; c++) unpk2(acc[r][c], vv[r][2 * c], vv[r][2 * c + 1]);

    int cb0 = col0 + tx * 4;
    int cb1 = cb0 + 64;
    #pragma unroll
    for (int r = 0; r < 8; r++) {
        int gr = row0 + (r < 4 ? ty * 4 + r : 64 + ty * 4 + (r - 4));
        if (gr >= Mrows) continue;
        size_t base = (size_t)gr * Ncols;
        if (cb0 + 4 <= Ncols) {
            *(float4*)&C[base + cb0] = make_float4(vv[r][0], vv[r][1], vv[r][2], vv[r][3]);
        } else {
            for (int c = 0; c < 4; c++)
                if (cb0 + c < Ncols) C[base + cb0 + c] = vv[r][c];
        }
        if (cb1 + 4 <= Ncols) {
            *(float4*)&C[base + cb1] = make_float4(vv[r][4], vv[r][5], vv[r][6], vv[r][7]);
        } else {
            for (int c = 0; c < 4; c++)
                if (cb1 + c < Ncols) C[base + cb1 + c] = vv[r][c + 4];
        }
    }

    if (bx > by) {
        int oc0 = row0 + ty * 4;
        int oc1 = row0 + 64 + ty * 4;
        #pragma unroll
        for (int c = 0; c < 8; c++) {
            int orow = col0 + tx * 4 + (c < 4 ? c : 64 + (c - 4));
            if (orow >= Ncols) continue;
            size_t base = (size_t)orow * Ncols;
            if (oc0 + 4 <= Mrows) {
                *(float4*)&C[base + oc0] =
                    make_float4(vv[0][c], vv[1][c], vv[2][c], vv[3][c]);
            } else {
                float vr[4] = {vv[0][c], vv[1][c], vv[2][c], vv[3][c]};
                for (int r = 0; r < 4; r++)
                    if (oc0 + r < Mrows) C[base + oc0 + r] = vr[r];
            }
            if (oc1 + 4 <= Mrows) {
                *(float4*)&C[base + oc1] =
                    make_float4(vv[4][c], vv[5][c], vv[6][c], vv[7][c]);
            } else {
                float vr[4] = {vv[4][c], vv[5][c], vv[6][c], vv[7][c]};
                for (int r = 0; r < 4; r++)
                    if (oc1 + r < Mrows) C[base + oc1 + r] = vr[r];
            }
        }
    }
}

// ---------------- sim (bf16 split-2 tensor, tiles by < SIM_SPLIT): R3-proven ----------------
#define SIMB_SMEM 73728

__global__ __launch_bounds__(256) void sim_bf16_kernel(
    const float* __restrict__ E, float* __restrict__ C)
{
    extern __shared__ unsigned su[];
    unsigned* Ahi = su;
    unsigned* Alo = su + 4608;
    unsigned* Bhi = su + 9216;
    unsigned* Blo = su + 13824;
    float* Csm = (float*)su;

    int bx = blockIdx.x, by = blockIdx.y;   // by in [0, SIM_SPLIT)
    if (bx < by) return;
    int row0 = by * 128, col0 = bx * 128;
    int t = threadIdx.x, lane = t & 31, warp = t >> 5;

    {
        int lr = t >> 1, half = t & 1;
        int ar = min(row0 + lr, NB_ITEMS - 1);
        int br = min(col0 + lr, NB_ITEMS - 1);
        const float4* ap = (const float4*)(E + (size_t)ar * 64 + half * 32);
        const float4* bp = (const float4*)(E + (size_t)br * 64 + half * 32);
        #pragma unroll
        for (int i = 0; i < 8; i++) {
            float4 av = ap[i];
            __nv_bfloat162 h0 = __float22bfloat162_rn(make_float2(av.x, av.y));
            float2 hf0 = __bfloat1622float2(h0);
            __nv_bfloat162 l0 = __float22bfloat162_rn(make_float2(av.x - hf0.x, av.y - hf0.y));
            __nv_bfloat162 h1 = __float22bfloat162_rn(make_float2(av.z, av.w));
            float2 hf1 = __bfloat1622float2(h1);
            __nv_bfloat162 l1 = __float22bfloat162_rn(make_float2(av.z - hf1.x, av.w - hf1.y));
            int w = lr * 36 + half * 16 + i * 2;
            Ahi[w] = *(unsigned*)&h0; Ahi[w + 1] = *(unsigned*)&h1;
            Alo[w] = *(unsigned*)&l0; Alo[w + 1] = *(unsigned*)&l1;

            float4 bv = bp[i];
            __nv_bfloat162 g0 = __float22bfloat162_rn(make_float2(bv.x, bv.y));
            float2 gf0 = __bfloat1622float2(g0);
            __nv_bfloat162 m0 = __float22bfloat162_rn(make_float2(bv.x - gf0.x, bv.y - gf0.y));
            __nv_bfloat162 g1 = __float22bfloat162_rn(make_float2(bv.z, bv.w));
            float2 gf1 = __bfloat1622float2(g1);
            __nv_bfloat162 m1 = __float22bfloat162_rn(make_float2(bv.z - gf1.x, bv.w - gf1.y));
            Bhi[w] = *(unsigned*)&g0; Bhi[w + 1] = *(unsigned*)&g1;
            Blo[w] = *(unsigned*)&m0; Blo[w + 1] = *(unsigned*)&m1;
        }
    }
    __syncthreads();

    float acc[4][4][4];
    #pragma unroll
    for (int mt = 0; mt < 4; mt++)
        #pragma unroll
        for (int nt = 0; nt < 4; nt++)
            #pragma unroll
            for (int q = 0; q < 4; q++) acc[mt][nt][q] = 0.f;

    int wm = warp >> 2, wn = warp & 3;
    int gr = lane >> 2, kq = lane & 3;

    #pragma unroll
    for (int kc = 0; kc < 4; kc++) {
        unsigned ah[4][4], al[4][4], bh[4][2], bl[4][2];
        #pragma unroll
        for (int mt = 0; mt < 4; mt++) {
            int r = wm * 64 + mt * 16 + gr;
            int w0 = r * 36 + kc * 8 + kq;
            ah[mt][0] = Ahi[w0];            ah[mt][1] = Ahi[w0 + 8 * 36];
            ah[mt][2] = Ahi[w0 + 4];        ah[mt][3] = Ahi[w0 + 8 * 36 + 4];
            al[mt][0] = Alo[w0];            al[mt][1] = Alo[w0 + 8 * 36];
            al[mt][2] = Alo[w0 + 4];        al[mt][3] = Alo[w0 + 8 * 36 + 4];
        }
        #pragma unroll
        for (int nt = 0; nt < 4; nt++) {
            int n = wn * 32 + nt * 8 + gr;
            int w0 = n * 36 + kc * 8 + kq;
            bh[nt][0] = Bhi[w0]; bh[nt][1] = Bhi[w0 + 4];
            bl[nt][0] = Blo[w0]; bl[nt][1] = Blo[w0 + 4];
        }
        #pragma unroll
        for (int mt = 0; mt < 4; mt++)
            #pragma unroll
            for (int nt = 0; nt < 4; nt++) {
                mma_bf16(acc[mt][nt], ah[mt], bh[nt]);
                mma_bf16(acc[mt][nt], ah[mt], bl[nt]);
                mma_bf16(acc[mt][nt], al[mt], bh[nt]);
            }
    }
    __syncthreads();

    #pragma unroll
    for (int mt = 0; mt < 4; mt++)
        #pragma unroll
        for (int nt = 0; nt < 4; nt++) {
            int r = wm * 64 + mt * 16 + gr;
            int c = wn * 32 + nt * 8 + kq * 2;
            *(float2*)&Csm[r * 132 + c]       = make_float2(acc[mt][nt][0], acc[mt][nt][1]);
            *(float2*)&Csm[(r + 8) * 132 + c] = make_float2(acc[mt][nt][2], acc[mt][nt][3]);
        }
    __syncthreads();

    {
        int r = t >> 1, half = t & 1;
        int grow = row0 + r;
        if (grow < NB_ITEMS) {
            int cbase = col0 + half * 64;
            #pragma unroll
            for (int i = 0; i < 16; i++) {
                int cc = cbase + 4 * i;
                if (cc + 4 <= NB_ITEMS)
                    *(float4*)&C[(size_t)grow * NB_ITEMS + cc] =
                        *(float4*)&Csm[r * 132 + half * 64 + 4 * i];
                else
                    for (int q = 0; q < 4; q++)
                        if (cc + q < NB_ITEMS)
                            C[(size_t)grow * NB_ITEMS + cc + q] = Csm[r * 132 + half * 64 + 4 * i + q];
            }
        }
    }
    if (bx > by) {
        int r = t >> 1, half = t & 1;
        int orow = col0 + r;
        if (orow < NB_ITEMS) {
            int cb = row0 + half * 64;
            #pragma unroll
            for (int i = 0; i < 16; i++) {
                int oc = cb + 4 * i;
                if (oc + 4 <= NB_ITEMS) {
                    float4 o;
                    o.x = Csm[(half * 64 + 4 * i + 0) * 132 + r];
                    o.y = Csm[(half * 64 + 4 * i + 1) * 132 + r];
                    o.z = Csm[(half * 64 + 4 * i + 2) * 132 + r];
                    o.w = Csm[(half * 64 + 4 * i + 3) * 132 + r];
                    *(float4*)&C[(size_t)orow * NB_ITEMS + oc] = o;
                }
            }
        }
    }
}

// ---------------- old-item corrections (unchanged, proven) ----------------
__global__ __launch_bounds__(256) void correction_kernel(
    const int* __restrict__ oldIt, const float* __restrict__ item_emb,
    float* __restrict__ out)
{
    __shared__ int   s_e[80];
    __shared__ int   s_first[80];
    __shared__ int   s_msk[80];
    __shared__ float s_delta[4][64];

    int b = blockIdx.x, t = threadIdx.x;
    int warp = t >> 5, lane = t & 31;

    if (t < 80) {
        int n = t / NOLDK, j = t % NOLDK;
        s_e[t] = oldIt[((size_t)n * BB + b) * NOLDK + j];
    }
    {
        int n = t >> 6, d = t & 63;
        s_delta[n][d] = g_final_each[((size_t)n * BB + b) * 64 + d]
                      - g_final[(size_t)b * 64 + d];
    }
    __syncthreads();
    if (t < 80) {
        int e = s_e[t], first = 1;
        for (int p = 0; p < t; p++) if (s_e[p] == e) { first = 0; break; }
        s_first[t] = first;
        int msk = 0;
        #pragma unroll
        for (int n = 0; n < 4; n++) {
            bool mem = false;
            #pragma unroll
            for (int q = 0; q < NOLDK; q++) mem = mem || (s_e[n * NOLDK + q] == e);
            if (mem) msk |= (1 << n);
        }
        s_msk[t] = msk;
    }
    __syncthreads();

    int eArr[10]; float v0[10], v1[10];
    #pragma unroll
    for (int q = 0; q < 10; q++) eArr[q] = s_e[warp * 10 + q];
    #pragma unroll
    for (int q = 0; q < 10; q++) {
        const float* p = item_emb + (size_t)(eArr[q] + 1) * 64;
        v0[q] = p[lane]; v1[q] = p[lane + 32];
    }
    #pragma unroll
    for (int q = 0; q < 10; q++) {
        int j = warp * 10 + q;
        if (!s_first[j]) continue;
        int msk = s_msk[j];
        float c0 = 0.f, c1 = 0.f;
        #pragma unroll
        for (int n = 0; n < 4; n++) {
            if (msk & (1 << n)) { c0 += s_delta[n][lane]; c1 += s_delta[n][lane + 32]; }
        }
        float dot = c0 * v0[q] + c1 * v1[q];
        #pragma unroll
        for (int o = 16; o > 0; o >>= 1) dot += __shfl_xor_sync(0xffffffffu, dot, o);
        if (lane == 0) out[(size_t)b * NB_ITEMS + eArr[q]] += dot;
    }
}

// ---------------- launch ----------------
extern "C" void kernel_launch(void* const* d_in, const int* in_sizes, int n_in,
                              void* d_out, int out_size)
{
    const int*   click    = (const int*)d_in[0];
    const int*   favor    = (const int*)d_in[1];
    const int*   cart     = (const int*)d_in[2];
    const int*   buy      = (const int*)d_in[3];
    const int*   userData = (const int*)d_in[4];
    const int*   oldIt    = (const int*)d_in[5];
    const float* item_emb = (const float*)d_in[6];
    const float* user_emb = (const float*)d_in[7];
    const float* user_wd  = (const float*)d_in[8];
    const float* omiga    = (const float*)d_in[9];
    const float* w_mix    = (const float*)d_in[10];
    const float* alpha    = (const float*)d_in[11];
    const float* gate_w   = (const float*)d_in[12];
    const float* gate_b   = (const float*)d_in[13];
    const float* Wk       = (const float*)d_in[14];
    const float* bk       = (const float*)d_in[15];
    const float* u_w      = (const float*)d_in[16];
    const float* u_b      = (const float*)d_in[17];
    float* out = (float*)d_out;

    void *pA = nullptr, *pB = nullptr;
    cudaGetSymbolAddress(&pA, g_Amat);
    cudaGetSymbolAddress(&pB, g_Bbig);

    static cudaStream_t s_fp32 = nullptr, s_bf16 = nullptr;
    static cudaEvent_t ev_fork = nullptr, ev_j1 = nullptr, ev_j2 = nullptr;
    if (s_fp32 == nullptr) {
        cudaStreamCreateWithFlags(&s_fp32, cudaStreamNonBlocking);
        cudaStreamCreateWithFlags(&s_bf16, cudaStreamNonBlocking);
        cudaEventCreateWithFlags(&ev_fork, cudaEventDisableTiming);
        cudaEventCreateWithFlags(&ev_j1, cudaEventDisableTiming);
        cudaEventCreateWithFlags(&ev_j2, cudaEventDisableTiming);
        cudaFuncSetAttribute(sim_kernel,
                             cudaFuncAttributeMaxDynamicSharedMemorySize, SIM_SMEM_B);
        cudaFuncSetAttribute(sim_bf16_kernel,
                             cudaFuncAttributeMaxDynamicSharedMemorySize, SIMB_SMEM);
        cudaFuncSetAttribute(score_bf16_kernel,
                             cudaFuncAttributeMaxDynamicSharedMemorySize, SC_SMEM);
    }

    cudaEventRecord(ev_fork, 0);
    cudaStreamWaitEvent(s_fp32, ev_fork, 0);
    cudaStreamWaitEvent(s_bf16, ev_fork, 0);

    // fp32 FFMA2 sim: tiles with by >= SIM_SPLIT
    {
        dim3 grid((NB_ITEMS + 127) / 128, (NB_ITEMS + 127) / 128 - SIM_SPLIT);
        sim_kernel<<<grid, 256, SIM_SMEM_B, s_fp32>>>(item_emb + 64, out + SIM_OFF);
    }
    cudaEventRecord(ev_j1, s_fp32);

    // bf16 tensor sim: tiles with by < SIM_SPLIT
    {
        dim3 grid((NB_ITEMS + 127) / 128, SIM_SPLIT);
        sim_bf16_kernel<<<grid, 256, SIMB_SMEM, s_bf16>>>(item_emb + 64, out + SIM_OFF);
    }
    cudaEventRecord(ev_j2, s_bf16);

    // main chain
    prep_kernel<<<(NB_ITEMS * 128 + 255) / 256, 256>>>(item_emb, u_w, omiga, out);

    batch_kernel<<<BB, 256>>>(click, favor, cart, buy, userData, item_emb, user_emb,
                              user_wd, w_mix, alpha, gate_w, gate_b, Wk, bk);

    {
        dim3 grid((NB_ITEMS + 127) / 128, BB / 128);
        score_bf16_kernel<<<grid, 256, SC_SMEM>>>((const float*)pA, (const float*)pB,
                                                  u_b, out);
    }

    correction_kernel<<<BB, 256>>>(oldIt, item_emb, out);

    cudaStreamWaitEvent(0, ev_j1, 0);
    cudaStreamWaitEvent(0, ev_j2, 0);
}

// round 17
// speedup vs baseline: 1.0883x; 1.0883x over previous
#include <cuda_runtime.h>
#include <cuda_bf16.h>

#define NB_ITEMS 12000
#define DD 64
#define BB 1024
#define LL 20
#define BKK 10
#define NOLDK 20

#define SIM_OFF   ((size_t)BB * NB_ITEMS)
#define OMIGA_OFF (SIM_OFF + (size_t)NB_ITEMS * NB_ITEMS)

// ---------------- scratch (static device globals; no allocation) ----------------
__device__ float g_final_each[4 * BB * DD];
__device__ float g_final[BB * DD];
__device__ float g_Amat[BB * 128];
__device__ float g_Bbig[(size_t)NB_ITEMS * 128];

// ---------------- helpers ----------------
typedef unsigned long long u64;
__device__ __forceinline__ u64 bcast2(float x) {
    u64 r; asm("mov.b64 %0, {%1, %1};" : "=l"(r) : "f"(x)); return r;
}
__device__ __forceinline__ void fma2(u64& d, u64 a, u64 b) {
    asm("fma.rn.f32x2 %0, %1, %2, %0;" : "+l"(d) : "l"(a), "l"(b));
}
__device__ __forceinline__ void unpk2(u64 v, float& lo, float& hi) {
    asm("mov.b64 {%0, %1}, %2;" : "=f"(lo), "=f"(hi) : "l"(v));
}
__device__ __forceinline__ float sigmoidf_(float x) { return 1.f / (1.f + expf(-x)); }

// bf16 MMA: D = A(16x16,row) * B(16x8,col) + D, fp32 accum (proven)
__device__ __forceinline__ void mma_bf16(float* c, const unsigned* a, const unsigned* b) {
    asm("mma.sync.aligned.m16n8k16.row.col.f32.bf16.bf16.f32 "
        "{%0,%1,%2,%3}, {%4,%5,%6,%7}, {%8,%9}, {%0,%1,%2,%3};"
        : "+f"(c[0]), "+f"(c[1]), "+f"(c[2]), "+f"(c[3])
        : "r"(a[0]), "r"(a[1]), "r"(a[2]), "r"(a[3]), "r"(b[0]), "r"(b[1]));
}

// ---------------- prep ----------------
__global__ __launch_bounds__(256) void prep_kernel(
    const float* __restrict__ item_emb, const float* __restrict__ u_w,
    const float* __restrict__ omiga, float* __restrict__ out)
{
    int idx = blockIdx.x * blockDim.x + threadIdx.x;
    if (idx < NB_ITEMS * 128) {
        int e = idx >> 7, k = idx & 127;
        g_Bbig[idx] = (k < 64) ? item_emb[(size_t)(e + 1) * 64 + k]
                               : u_w[(size_t)(k - 64) * NB_ITEMS + e];
    }
    if (idx < NB_ITEMS) out[OMIGA_OFF + idx] = omiga[idx + 1];
}

// ---------------- per-batch front-end (proven) ----------------
__global__ __launch_bounds__(256) void batch_kernel(
    const int* __restrict__ click, const int* __restrict__ favor,
    const int* __restrict__ cart, const int* __restrict__ buy,
    const int* __restrict__ userData,
    const float* __restrict__ item_emb, const float* __restrict__ user_emb,
    const float* __restrict__ user_wd, const float* __restrict__ w_mix,
    const float* __restrict__ alpha, const float* __restrict__ gate_w,
    const float* __restrict__ gate_b, const float* __restrict__ Wk,
    const float* __restrict__ bk)
{
    __shared__ float s_bask[4][LL][DD];
    __shared__ int   s_idx[4][LL][BKK];
    __shared__ float s_eu[DD];
    __shared__ float s_scp[4][2][LL];
    __shared__ float s_attn[4][LL];
    __shared__ float s_mask[4][LL];
    __shared__ float s_lvec[4][DD];
    __shared__ float s_s1[4][DD], s_s2[4][DD], s_s3[4][DD], s_fn[4][DD];
    __shared__ float s_g[8];
    __shared__ float s_fm[DD], s_lm[DD];

    int b = blockIdx.x, t = threadIdx.x;
    int lane = t & 31, warp = t >> 5;
    int u = userData[b];
    const int* srcs[4] = {click, favor, cart, buy};

    for (int i = t; i < 4 * LL * BKK; i += 256) {
        int n = i / (LL * BKK), r = i % (LL * BKK);
        s_idx[n][r / BKK][r % BKK] = srcs[n][(size_t)b * LL * BKK + r];
    }
    if (t < 64) s_eu[t] = user_emb[(size_t)u * 64 + t];
    __syncthreads();

    for (int i = t; i < 4 * LL * DD; i += 256) {
        int n = i / (LL * DD), rem = i % (LL * DD), l = rem / DD, d = rem & 63;
        float s = 0.f;
        #pragma unroll
        for (int q = 0; q < BKK; q++) s += item_emb[(size_t)s_idx[n][l][q] * 64 + d];
        s_bask[n][l][d] = s;
    }
    __syncthreads();

    if (t < 80) {
        int n = t / LL, l = t % LL;
        float m = 0.f;
        for (int d = 0; d < DD; d++) m += s_bask[n][l][d];
        s_mask[n][l] = (m != 0.f) ? 1.f : 0.f;
    }

    {
        int n = t >> 6, e = t & 63;
        float acc[LL];
        #pragma unroll
        for (int l = 0; l < LL; l++) acc[l] = bk[n * 64 + e];
        for (int d0 = 0; d0 < DD; d0++) {
            float w = Wk[((size_t)n * 64 + d0) * 64 + e];
            #pragma unroll
            for (int l = 0; l < LL; l++) acc[l] += s_bask[n][l][d0] * w;
        }
        float eu = s_eu[e];
        #pragma unroll
        for (int l = 0; l < LL; l++) {
            float v = fmaxf(acc[l], 0.f) * eu;
            #pragma unroll
            for (int o = 16; o > 0; o >>= 1) v += __shfl_xor_sync(0xffffffffu, v, o);
            if (lane == 0) s_scp[n][e >> 5][l] = v;
        }
    }
    __syncthreads();

    if (warp < 4) {
        int n = warp;
        float sc = -1e30f;
        if (lane < LL) {
            sc = (s_scp[n][0][lane] + s_scp[n][1][lane]) * 0.125f;
            if (s_mask[n][lane] == 0.f) sc = -1e9f;
        }
        float mx = sc;
        #pragma unroll
        for (int o = 16; o > 0; o >>= 1) mx = fmaxf(mx, __shfl_xor_sync(0xffffffffu, mx, o));
        float ex = (lane < LL) ? expf(sc - mx) : 0.f;
        float sm = ex;
        #pragma unroll
        for (int o = 16; o > 0; o >>= 1) sm += __shfl_xor_sync(0xffffffffu, sm, o);
        if (lane < LL) s_attn[n][lane] = ex / sm;
    }
    __syncthreads();

    {
        int n = t >> 6, d = t & 63;
        float lv = 0.f;
        #pragma unroll
        for (int l = 0; l < LL; l++) lv += s_attn[n][l] * s_bask[n][l][d];
        s_lvec[n][d] = lv;
        float w1 = sigmoidf_(user_wd[(size_t)u * 8 + 2 * n]);
        float w2 = sigmoidf_(user_wd[(size_t)u * 8 + 2 * n + 1]);
        float coef = 1.f - w2 * w1;
        float h = s_bask[n][0][d];
        #pragma unroll
        for (int l = 1; l < LL; l++) h = w1 * h + coef * s_bask[n][l][d];
        float s1 = h;
        h = s_bask[n][10][d];
        #pragma unroll
        for (int l = 11; l < LL; l++) h = w1 * h + coef * s_bask[n][l][d];
        float s2 = h;
        float s3 = w1 * s_bask[n][18][d] + coef * s_bask[n][19][d];
        float a0 = alpha[0], a1 = alpha[1];
        float fn = s1 + a0 * (s1 - s2) + a1 * (s1 - s3);
        s_s1[n][d] = s1; s_s2[n][d] = s2; s_s3[n][d] = s3; s_fn[n][d] = fn;
    }
    __syncthreads();

    if (warp < 4) {
        int n = warp;
        float x = s_fn[n][lane] * gate_w[lane] + s_fn[n][lane + 32] * gate_w[lane + 32]
                + s_lvec[n][lane] * gate_w[64 + lane] + s_lvec[n][lane + 32] * gate_w[96 + lane];
        #pragma unroll
        for (int o = 16; o > 0; o >>= 1) x += __shfl_xor_sync(0xffffffffu, x, o);
        if (lane == 0) s_g[n] = sigmoidf_(x + gate_b[0]);
    }
    __syncthreads();

    {
        int n = t >> 6, d = t & 63;
        float g = s_g[n];
        g_final_each[((size_t)n * BB + b) * 64 + d] = g * s_fn[n][d] + (1.f - g) * s_lvec[n][d];
    }

    if (t < 64) {
        int d = t;
        float wmx[4][4];
        #pragma unroll
        for (int i = 0; i < 4; i++) {
            float mx = -1e30f;
            #pragma unroll
            for (int j = 0; j < 4; j++) mx = fmaxf(mx, w_mix[i * 4 + j]);
            float s = 0.f;
            #pragma unroll
            for (int j = 0; j < 4; j++) { wmx[i][j] = expf(w_mix[i * 4 + j] - mx); s += wmx[i][j]; }
            #pragma unroll
            for (int j = 0; j < 4; j++) wmx[i][j] /= s;
        }
        float s1m = 0, s2m = 0, s3m = 0, lm = 0;
        #pragma unroll
        for (int n = 0; n < 4; n++) {
            s1m += wmx[0][n] * s_s1[n][d];
            s2m += wmx[1][n] * s_s2[n][d];
            s3m += wmx[2][n] * s_s3[n][d];
            lm  += wmx[3][n] * s_lvec[n][d];
        }
        float a0 = alpha[0], a1 = alpha[1];
        s_fm[d] = s1m + a0 * (s1m - s2m) + a1 * (s1m - s3m);
        s_lm[d] = lm;
    }
    __syncthreads();

    if (warp == 0) {
        float x = s_fm[lane] * gate_w[lane] + s_fm[lane + 32] * gate_w[lane + 32]
                + s_lm[lane] * gate_w[64 + lane] + s_lm[lane + 32] * gate_w[96 + lane];
        #pragma unroll
        for (int o = 16; o > 0; o >>= 1) x += __shfl_xor_sync(0xffffffffu, x, o);
        if (lane == 0) s_g[4] = sigmoidf_(x + gate_b[0]);
    }
    __syncthreads();

    if (t < 64) {
        float gm = s_g[4];
        float fin = gm * s_fm[t] + (1.f - gm) * s_lm[t];
        g_final[(size_t)b * 64 + t] = fin;
        g_Amat[(size_t)b * 128 + t] = fin;
        g_Amat[(size_t)b * 128 + 64 + t] = s_eu[t];
    }
}

// ---------------- score GEMM on the TENSOR pipe: bf16 split-2 mma.sync (R15-proven) ----------------
#define SC_PITCH 68
#define SC_SMEM  (4 * 128 * SC_PITCH * 4)   /* 139264 B */

__global__ __launch_bounds__(256) void score_bf16_kernel(
    const float* __restrict__ A, const float* __restrict__ B,
    const float* __restrict__ bias, float* __restrict__ C)
{
    extern __shared__ unsigned su[];
    unsigned* Ahi = su;
    unsigned* Alo = su + 128 * SC_PITCH;
    unsigned* Bhi = su + 2 * 128 * SC_PITCH;
    unsigned* Blo = su + 3 * 128 * SC_PITCH;

    int bx = blockIdx.x, by = blockIdx.y;
    int row0 = by * 128, col0 = bx * 128;
    int t = threadIdx.x, lane = t & 31, warp = t >> 5;

    // load + split fp32 -> (hi, lo) bf16 pairs
    {
        int lr = t >> 1, half = t & 1;
        int ar = row0 + lr;                               // rows: 1024 exact
        int br = min(col0 + lr, NB_ITEMS - 1);
        const float4* ap = (const float4*)(A + (size_t)ar * 128 + half * 64);
        const float4* bp = (const float4*)(B + (size_t)br * 128 + half * 64);
        #pragma unroll
        for (int i = 0; i < 16; i++) {
            float4 av = ap[i];
            __nv_bfloat162 h0 = __float22bfloat162_rn(make_float2(av.x, av.y));
            float2 hf0 = __bfloat1622float2(h0);
            __nv_bfloat162 l0 = __float22bfloat162_rn(make_float2(av.x - hf0.x, av.y - hf0.y));
            __nv_bfloat162 h1 = __float22bfloat162_rn(make_float2(av.z, av.w));
            float2 hf1 = __bfloat1622float2(h1);
            __nv_bfloat162 l1 = __float22bfloat162_rn(make_float2(av.z - hf1.x, av.w - hf1.y));
            int w = lr * SC_PITCH + half * 32 + i * 2;
            Ahi[w] = *(unsigned*)&h0; Ahi[w + 1] = *(unsigned*)&h1;
            Alo[w] = *(unsigned*)&l0; Alo[w + 1] = *(unsigned*)&l1;

            float4 bv = bp[i];
            __nv_bfloat162 g0 = __float22bfloat162_rn(make_float2(bv.x, bv.y));
            float2 gf0 = __bfloat1622float2(g0);
            __nv_bfloat162 m0 = __float22bfloat162_rn(make_float2(bv.x - gf0.x, bv.y - gf0.y));
            __nv_bfloat162 g1 = __float22bfloat162_rn(make_float2(bv.z, bv.w));
            float2 gf1 = __bfloat1622float2(g1);
            __nv_bfloat162 m1 = __float22bfloat162_rn(make_float2(bv.z - gf1.x, bv.w - gf1.y));
            Bhi[w] = *(unsigned*)&g0; Bhi[w + 1] = *(unsigned*)&g1;
            Blo[w] = *(unsigned*)&m0; Blo[w + 1] = *(unsigned*)&m1;
        }
    }
    __syncthreads();

    float acc[4][4][4];
    #pragma unroll
    for (int mt = 0; mt < 4; mt++)
        #pragma unroll
        for (int nt = 0; nt < 4; nt++)
            #pragma unroll
            for (int q = 0; q < 4; q++) acc[mt][nt][q] = 0.f;

    int wm = warp >> 2, wn = warp & 3;
    int gr = lane >> 2, kq = lane & 3;

    #pragma unroll
    for (int kc = 0; kc < 8; kc++) {
        unsigned ah[4][4], al[4][4], bh[4][2], bl[4][2];
        #pragma unroll
        for (int mt = 0; mt < 4; mt++) {
            int r = wm * 64 + mt * 16 + gr;
            int w0 = r * SC_PITCH + kc * 8 + kq;
            ah[mt][0] = Ahi[w0];                 ah[mt][1] = Ahi[w0 + 8 * SC_PITCH];
            ah[mt][2] = Ahi[w0 + 4];             ah[mt][3] = Ahi[w0 + 8 * SC_PITCH + 4];
            al[mt][0] = Alo[w0];                 al[mt][1] = Alo[w0 + 8 * SC_PITCH];
            al[mt][2] = Alo[w0 + 4];             al[mt][3] = Alo[w0 + 8 * SC_PITCH + 4];
        }
        #pragma unroll
        for (int nt = 0; nt < 4; nt++) {
            int n = wn * 32 + nt * 8 + gr;
            int w0 = n * SC_PITCH + kc * 8 + kq;
            bh[nt][0] = Bhi[w0]; bh[nt][1] = Bhi[w0 + 4];
            bl[nt][0] = Blo[w0]; bl[nt][1] = Blo[w0 + 4];
        }
        #pragma unroll
        for (int mt = 0; mt < 4; mt++)
            #pragma unroll
            for (int nt = 0; nt < 4; nt++) {
                mma_bf16(acc[mt][nt], ah[mt], bh[nt]);
                mma_bf16(acc[mt][nt], ah[mt], bl[nt]);
                mma_bf16(acc[mt][nt], al[mt], bh[nt]);
            }
    }

    // epilogue: direct fragment write + bias
    #pragma unroll
    for (int mt = 0; mt < 4; mt++)
        #pragma unroll
        for (int nt = 0; nt < 4; nt++) {
            int r = wm * 64 + mt * 16 + gr;
            int c = wn * 32 + nt * 8 + kq * 2;
            int gc = col0 + c;
            size_t b0 = (size_t)(row0 + r) * NB_ITEMS;
            size_t b1 = (size_t)(row0 + r + 8) * NB_ITEMS;
            if (gc < NB_ITEMS)     { float bb = bias[gc];
                                     C[b0 + gc] = acc[mt][nt][0] + bb;
                                     C[b1 + gc] = acc[mt][nt][2] + bb; }
            if (gc + 1 < NB_ITEMS) { float bb = bias[gc + 1];
                                     C[b0 + gc + 1] = acc[mt][nt][1] + bb;
                                     C[b1 + gc + 1] = acc[mt][nt][3] + bb; }
        }
}

// ---------------- sim: K-resident 128x128, proven R9 kernel ----------------
#define SIM_SMEM_B (64 * 1024)

__global__ __launch_bounds__(256) void sim_kernel(
    const float* __restrict__ E, float* __restrict__ C)
{
    extern __shared__ float sm[];
    float* As = sm;
    float* Bs = sm + 64 * 128;

    int bx = blockIdx.x, by = blockIdx.y;
    if (bx < by) return;
    int t = threadIdx.x;
    int tx = t & 15, ty = t >> 4;
    int row0 = by * 128, col0 = bx * 128;
    int Mrows = NB_ITEMS, Ncols = NB_ITEMS;

    {
        int lr = t >> 1, kh = (t & 1) * 32;
        int ar = min(row0 + lr, NB_ITEMS - 1);
        int br = min(col0 + lr, NB_ITEMS - 1);
        const float4* ap = (const float4*)(E + (size_t)ar * 64 + kh);
        const float4* bp = (const float4*)(E + (size_t)br * 64 + kh);
        #pragma unroll
        for (int i = 0; i < 8; i++) {
            float4 a = ap[i];
            float4 b = bp[i];
            int k = kh + i * 4;
            As[(k + 0) * 128 + lr] = a.x; As[(k + 1) * 128 + lr] = a.y;
            As[(k + 2) * 128 + lr] = a.z; As[(k + 3) * 128 + lr] = a.w;
            Bs[(k + 0) * 128 + lr] = b.x; Bs[(k + 1) * 128 + lr] = b.y;
            Bs[(k + 2) * 128 + lr] = b.z; Bs[(k + 3) * 128 + lr] = b.w;
        }
    }
    __syncthreads();

    u64 acc[8][4];
    #pragma unroll
    for (int r = 0; r < 8; r++)
        #pragma unroll
        for (int c = 0; c < 4; c++) acc[r][c] = 0ULL;

    #pragma unroll 8
    for (int k = 0; k < 64; k++) {
        float4 fa0 = *(const float4*)&As[k * 128 + ty * 4];
        float4 fa1 = *(const float4*)&As[k * 128 + 64 + ty * 4];
        const u64* pb0 = (const u64*)&Bs[k * 128 + tx * 4];
        const u64* pb1 = (const u64*)&Bs[k * 128 + 64 + tx * 4];
        u64 bq0 = pb0[0], bq1 = pb0[1], bq2 = pb1[0], bq3 = pb1[1];
        float a[8] = {fa0.x, fa0.y, fa0.z, fa0.w, fa1.x, fa1.y, fa1.z, fa1.w};
        #pragma unroll
        for (int r = 0; r < 8; r++) {
            u64 ar = bcast2(a[r]);
            fma2(acc[r][0], ar, bq0);
            fma2(acc[r][1], ar, bq1);
            fma2(acc[r][2], ar, bq2);
            fma2(acc[r][3], ar, bq3);
        }
    }

    float vv[8][8];
    #pragma unroll
    for (int r = 0; r < 8; r++)
        #pragma unroll
        for (int c = 0; c < 4; c++) unpk2(acc[r][c], vv[r][2 * c], vv[r][2 * c + 1]);

    int cb0 = col0 + tx * 4;
    int cb1 = cb0 + 64;
    #pragma unroll
    for (int r = 0; r < 8; r++) {
        int gr = row0 + (r < 4 ? ty * 4 + r : 64 + ty * 4 + (r - 4));
        if (gr >= Mrows) continue;
        size_t base = (size_t)gr * Ncols;
        if (cb0 + 4 <= Ncols) {
            *(float4*)&C[base + cb0] = make_float4(vv[r][0], vv[r][1], vv[r][2], vv[r][3]);
        } else {
            for (int c = 0; c < 4; c++)
                if (cb0 + c < Ncols) C[base + cb0 + c] = vv[r][c];
        }
        if (cb1 + 4 <= Ncols) {
            *(float4*)&C[base + cb1] = make_float4(vv[r][4], vv[r][5], vv[r][6], vv[r][7]);
        } else {
            for (int c = 0; c < 4; c++)
                if (cb1 + c < Ncols) C[base + cb1 + c] = vv[r][c + 4];
        }
    }

    if (bx > by) {
        int oc0 = row0 + ty * 4;
        int oc1 = row0 + 64 + ty * 4;
        #pragma unroll
        for (int c = 0; c < 8; c++) {
            int orow = col0 + tx * 4 + (c < 4 ? c : 64 + (c - 4));
            if (orow >= Ncols) continue;
            size_t base = (size_t)orow * Ncols;
            if (oc0 + 4 <= Mrows) {
                *(float4*)&C[base + oc0] =
                    make_float4(vv[0][c], vv[1][c], vv[2][c], vv[3][c]);
            } else {
                float vr[4] = {vv[0][c], vv[1][c], vv[2][c], vv[3][c]};
                for (int r = 0; r < 4; r++)
                    if (oc0 + r < Mrows) C[base + oc0 + r] = vr[r];
            }
            if (oc1 + 4 <= Mrows) {
                *(float4*)&C[base + oc1] =
                    make_float4(vv[4][c], vv[5][c], vv[6][c], vv[7][c]);
            } else {
                float vr[4] = {vv[4][c], vv[5][c], vv[6][c], vv[7][c]};
                for (int r = 0; r < 4; r++)
                    if (oc1 + r < Mrows) C[base + oc1 + r] = vr[r];
            }
        }
    }
}

// ---------------- old-item corrections (proven) ----------------
__global__ __launch_bounds__(256) void correction_kernel(
    const int* __restrict__ oldIt, const float* __restrict__ item_emb,
    float* __restrict__ out)
{
    __shared__ int   s_e[80];
    __shared__ int   s_first[80];
    __shared__ int   s_msk[80];
    __shared__ float s_delta[4][64];

    int b = blockIdx.x, t = threadIdx.x;
    int warp = t >> 5, lane = t & 31;

    if (t < 80) {
        int n = t / NOLDK, j = t % NOLDK;
        s_e[t] = oldIt[((size_t)n * BB + b) * NOLDK + j];
    }
    {
        int n = t >> 6, d = t & 63;
        s_delta[n][d] = g_final_each[((size_t)n * BB + b) * 64 + d]
                      - g_final[(size_t)b * 64 + d];
    }
    __syncthreads();
    if (t < 80) {
        int e = s_e[t], first = 1;
        for (int p = 0; p < t; p++) if (s_e[p] == e) { first = 0; break; }
        s_first[t] = first;
        int msk = 0;
        #pragma unroll
        for (int n = 0; n < 4; n++) {
            bool mem = false;
            #pragma unroll
            for (int q = 0; q < NOLDK; q++) mem = mem || (s_e[n * NOLDK + q] == e);
            if (mem) msk |= (1 << n);
        }
        s_msk[t] = msk;
    }
    __syncthreads();

    int eArr[10]; float v0[10], v1[10];
    #pragma unroll
    for (int q = 0; q < 10; q++) eArr[q] = s_e[warp * 10 + q];
    #pragma unroll
    for (int q = 0; q < 10; q++) {
        const float* p = item_emb + (size_t)(eArr[q] + 1) * 64;
        v0[q] = p[lane]; v1[q] = p[lane + 32];
    }
    #pragma unroll
    for (int q = 0; q < 10; q++) {
        int j = warp * 10 + q;
        if (!s_first[j]) continue;
        int msk = s_msk[j];
        float c0 = 0.f, c1 = 0.f;
        #pragma unroll
        for (int n = 0; n < 4; n++) {
            if (msk & (1 << n)) { c0 += s_delta[n][lane]; c1 += s_delta[n][lane + 32]; }
        }
        float dot = c0 * v0[q] + c1 * v1[q];
        #pragma unroll
        for (int o = 16; o > 0; o >>= 1) dot += __shfl_xor_sync(0xffffffffu, dot, o);
        if (lane == 0) out[(size_t)b * NB_ITEMS + eArr[q]] += dot;
    }
}

// ---------------- launch ----------------
extern "C" void kernel_launch(void* const* d_in, const int* in_sizes, int n_in,
                              void* d_out, int out_size)
{
    const int*   click    = (const int*)d_in[0];
    const int*   favor    = (const int*)d_in[1];
    const int*   cart     = (const int*)d_in[2];
    const int*   buy      = (const int*)d_in[3];
    const int*   userData = (const int*)d_in[4];
    const int*   oldIt    = (const int*)d_in[5];
    const float* item_emb = (const float*)d_in[6];
    const float* user_emb = (const float*)d_in[7];
    const float* user_wd  = (const float*)d_in[8];
    const float* omiga    = (const float*)d_in[9];
    const float* w_mix    = (const float*)d_in[10];
    const float* alpha    = (const float*)d_in[11];
    const float* gate_w   = (const float*)d_in[12];
    const float* gate_b   = (const float*)d_in[13];
    const float* Wk       = (const float*)d_in[14];
    const float* bk       = (const float*)d_in[15];
    const float* u_w      = (const float*)d_in[16];
    const float* u_b      = (const float*)d_in[17];
    float* out = (float*)d_out;

    void *pA = nullptr, *pB = nullptr;
    cudaGetSymbolAddress(&pA, g_Amat);
    cudaGetSymbolAddress(&pB, g_Bbig);

    static cudaStream_t s_side = nullptr;
    static cudaEvent_t ev_fork = nullptr, ev_join = nullptr;
    if (s_side == nullptr) {
        cudaStreamCreateWithFlags(&s_side, cudaStreamNonBlocking);
        cudaEventCreateWithFlags(&ev_fork, cudaEventDisableTiming);
        cudaEventCreateWithFlags(&ev_join, cudaEventDisableTiming);
        cudaFuncSetAttribute(sim_kernel,
                             cudaFuncAttributeMaxDynamicSharedMemorySize, SIM_SMEM_B);
        cudaFuncSetAttribute(score_bf16_kernel,
                             cudaFuncAttributeMaxDynamicSharedMemorySize, SC_SMEM);
    }

    // Fork: sim on side stream (FMA pipe), chain + tensor-pipe score on main stream.
    cudaEventRecord(ev_fork, 0);
    cudaStreamWaitEvent(s_side, ev_fork, 0);
    {
        dim3 grid((NB_ITEMS + 127) / 128, (NB_ITEMS + 127) / 128);
        sim_kernel<<<grid, 256, SIM_SMEM_B, s_side>>>(item_emb + 64, out + SIM_OFF);
    }
    cudaEventRecord(ev_join, s_side);

    prep_kernel<<<(NB_ITEMS * 128 + 255) / 256, 256>>>(item_emb, u_w, omiga, out);

    batch_kernel<<<BB, 256>>>(click, favor, cart, buy, userData, item_emb, user_emb,
                              user_wd, w_mix, alpha, gate_w, gate_b, Wk, bk);

    // score GEMM on the tensor pipe (no FMA contention with sim)
    {
        dim3 grid((NB_ITEMS + 127) / 128, BB / 128);
        score_bf16_kernel<<<grid, 256, SC_SMEM>>>((const float*)pA, (const float*)pB,
                                                  u_b, out);
    }

    correction_kernel<<<BB, 256>>>(oldIt, item_emb, out);

    cudaStreamWaitEvent(0, ev_join, 0);
}